// round 15
// baseline (speedup 1.0000x reference)
#include <cuda_runtime.h>
#include <cuda_fp16.h>
#include <cstdint>

#define R_TOT   48
#define N_NODES 1000
#define RN      48000          // R_TOT * N_NODES
#define E_IN    12000
#define F_DIM   64
#define HC      256            // H * C
#define H_HEADS 4
#define BKT     96             // bucket capacity: mean deg 12, 24 sigma margin

// ---------------- scratch (static device globals; no allocation) -------------
// h stored as fp16, row-major [RN][256] halves (viewed as [RN][32] uint4 by k_agg)
__device__ uint4  g_hv[(size_t)RN * 32];
__device__ float  g_asrc[RN * H_HEADS];
__device__ float  g_adst[RN * H_HEADS];
__device__ float4 g_Wf[8 * 32 * 32];    // pre-split W fragments: [kstep][ntile][lane]
__device__ int    g_cursor[N_NODES];    // bucket fill count (init 1 by k_prep)
__device__ int    g_bkt[N_NODES * BKT]; // incoming-edge sources per node
__device__ int    g_is32;

// ---------------- packed / tf32 helpers ---------------------------------------
union F2U { unsigned long long u; float2 f; };
__device__ __forceinline__ unsigned long long fma2(unsigned long long a,
                                                   unsigned long long b,
                                                   unsigned long long c) {
    unsigned long long d;
    asm("fma.rn.f32x2 %0, %1, %2, %3;" : "=l"(d) : "l"(a), "l"(b), "l"(c));
    return d;
}

__device__ __forceinline__ unsigned tf32_rna(float v) {
    unsigned r;
    asm("cvt.rna.tf32.f32 %0, %1;" : "=r"(r) : "f"(v));
    return r;
}

#define MMA_TF32(d, a, b0, b1)                                                  \
    asm volatile("mma.sync.aligned.m16n8k8.row.col.f32.tf32.tf32.f32 "          \
                 "{%0,%1,%2,%3}, {%4,%5,%6,%7}, {%8,%9}, {%0,%1,%2,%3};"        \
                 : "+f"((d)[0]), "+f"((d)[1]), "+f"((d)[2]), "+f"((d)[3])       \
                 : "r"((a)[0]), "r"((a)[1]), "r"((a)[2]), "r"((a)[3]),          \
                   "r"(b0), "r"(b1))

// ---------------- prep: W split + bucket init ----------------------------------
// Blocks [0,32): pre-split W into mma B-fragment order.
// Blocks [32,36): per-node cursor=1 and self-loop in slot 0 (deterministic).
// Original self-loops are dropped (reference masks them to -inf => exp == 0).
__global__ __launch_bounds__(256) void k_prep(const float* __restrict__ W) {
    int t = threadIdx.x;
    if (blockIdx.x < 32) {
        int i = blockIdx.x * 256 + t;            // 0..8191
        int lane = i & 31, ntg = (i >> 5) & 31, ks = i >> 10;
        int t4 = lane & 3, g = lane >> 2;
        int col = ntg * 8 + g;
        float b0 = W[(ks * 8 + t4) * HC + col];
        float b1 = W[(ks * 8 + t4 + 4) * HC + col];
        unsigned b0h = tf32_rna(b0), b1h = tf32_rna(b1);
        unsigned b0l = tf32_rna(b0 - __uint_as_float(b0h));
        unsigned b1l = tf32_rna(b1 - __uint_as_float(b1h));
        g_Wf[i] = make_float4(__uint_as_float(b0h), __uint_as_float(b1h),
                              __uint_as_float(b0l), __uint_as_float(b1l));
        return;
    }
    int i = (blockIdx.x - 32) * 256 + t;
    if (i < N_NODES) {
        g_cursor[i] = 1;
        g_bkt[i * BKT] = i;              // added self-loop, slot 0
    }
}

// Width detect by sampling: if edge_index is int64 (values < 1000), EVERY odd
// 32-bit word is zero. 32 sampled odd words all zero on int32 random data has
// probability ~1e-96. Sampled positions stay within the first 24000 words.
__device__ __forceinline__ int detect_is32_warp(const int* e32, int lane) {
    int f = (e32[2 * (lane * 375) + 1] != 0);
    unsigned b = __ballot_sync(0xffffffffu, f);
    return b != 0;
}

// Single-pass bucketed scatter: p = atomicAdd(cursor[d]); bkt[d*BKT+p] = s.
__global__ __launch_bounds__(256) void k_scatter(const void* __restrict__ ei) {
    __shared__ int s_is32;
    const int* e32 = (const int*)ei;
    const long long* e64 = (const long long*)ei;
    int t = threadIdx.x;
    if (t < 32) {
        int is32 = detect_is32_warp(e32, t);
        if (t == 0) s_is32 = is32;
    }
    __syncthreads();
    int is32 = s_is32;
    int e = blockIdx.x * 256 + t;
    if (e < E_IN) {
        int s = is32 ? e32[e] : (int)e64[e];
        int d = is32 ? e32[E_IN + e] : (int)e64[E_IN + e];
        if (s != d) {
            int p = atomicAdd(&g_cursor[d], 1);
            if (p < BKT) g_bkt[d * BKT + p] = s;
        }
    }
}

// ---------------- projection GEMM (tensor cores, 3xTF32) + logits -------------
// Warp tile 16 rows x 64 cols (one m16 tile), 4 blocks/SM, grid 1500.
// A-path: x tile staged in smem (coalesced in, conflict-free LDS out).
// Epilogue: results transposed through smem (aliased over the x buffer) so h is
// written with coalesced STG.128 (128 wavefronts/block vs ~1024 scattered).
// One head per warp -> logits close with a 4-lane quad reduction.
// D = Xhi*Whi + Xhi*Wlo + Xlo*Whi (fp32 accum): error ~1e-7.
#define HROW 132                         // half2 stride per row (528B, conflict-free)
__global__ __launch_bounds__(256, 4) void k_gemm(const float* __restrict__ x,
                                                 const float* __restrict__ attS,
                                                 const float* __restrict__ attD) {
    __shared__ __align__(16) char s_buf[32 * HROW * 4];   // 16.9 KB (sX then sH)
    __shared__ float sAS[HC], sAD[HC];
    float* sX = (float*)s_buf;            // 32 rows x stride 68 floats (8.7 KB)
    __half2* sH = (__half2*)s_buf;        // 32 rows x stride 132 half2
    int t = threadIdx.x, warp = t >> 5, lane = t & 31;
    int g = lane >> 2, t4 = lane & 3;
    int mg = warp >> 2, ng = warp & 3;
    int rowBase = blockIdx.x * 32;

    // stage x tile: 32 rows x 16 float4, 2 per thread, coalesced
    for (int i = t; i < 32 * 16; i += 256) {
        int row = i >> 4, j4 = i & 15;
        float4 v = ((const float4*)(x + (size_t)(rowBase + row) * F_DIM))[j4];
        *(float4*)&sX[row * 68 + j4 * 4] = v;
    }
    if (t < HC) { sAS[t] = attS[t]; sAD[t] = attD[t]; }
    __syncthreads();

    float acc[8][4];
#pragma unroll
    for (int nt = 0; nt < 8; nt++)
#pragma unroll
        for (int j = 0; j < 4; j++) acc[nt][j] = 0.f;

    const float* xr0 = sX + (mg * 16 + g) * 68 + t4;

#pragma unroll
    for (int ks = 0; ks < 8; ks++) {
        unsigned ah[4], al[4];
        {
            const float* xr = xr0 + ks * 8;
            float v0 = xr[0];            // (row g,    col t4)
            float v1 = xr[8 * 68];       // (row g+8,  col t4)
            float v2 = xr[4];            // (row g,    col t4+4)
            float v3 = xr[8 * 68 + 4];
            ah[0] = tf32_rna(v0); al[0] = tf32_rna(v0 - __uint_as_float(ah[0]));
            ah[1] = tf32_rna(v1); al[1] = tf32_rna(v1 - __uint_as_float(ah[1]));
            ah[2] = tf32_rna(v2); al[2] = tf32_rna(v2 - __uint_as_float(ah[2]));
            ah[3] = tf32_rna(v3); al[3] = tf32_rna(v3 - __uint_as_float(ah[3]));
        }
#pragma unroll
        for (int nt = 0; nt < 8; nt++) {
            float4 b = g_Wf[((size_t)ks * 32 + ng * 8 + nt) * 32 + lane];  // LDG.128
            unsigned b0h = __float_as_uint(b.x), b1h = __float_as_uint(b.y);
            unsigned b0l = __float_as_uint(b.z), b1l = __float_as_uint(b.w);
            MMA_TF32(acc[nt], ah, b0h, b1h);
            MMA_TF32(acc[nt], ah, b0l, b1l);
            MMA_TF32(acc[nt], al, b0h, b1h);
        }
    }

    // logits for this warp's head (= ng) from register fragments
    int head = ng, n0 = ng * 64;
    int lrow0 = mg * 16 + g;                     // local rows lrow0, lrow0+8
    {
        float as0 = 0.f, ad0 = 0.f, as1 = 0.f, ad1 = 0.f;
#pragma unroll
        for (int nt = 0; nt < 8; nt++) {
            int c = n0 + nt * 8 + 2 * t4;
            float* a = acc[nt];
            as0 += a[0] * sAS[c] + a[1] * sAS[c + 1];
            ad0 += a[0] * sAD[c] + a[1] * sAD[c + 1];
            as1 += a[2] * sAS[c] + a[3] * sAS[c + 1];
            ad1 += a[2] * sAD[c] + a[3] * sAD[c + 1];
        }
        as0 += __shfl_xor_sync(0xffffffffu, as0, 1); as0 += __shfl_xor_sync(0xffffffffu, as0, 2);
        ad0 += __shfl_xor_sync(0xffffffffu, ad0, 1); ad0 += __shfl_xor_sync(0xffffffffu, ad0, 2);
        as1 += __shfl_xor_sync(0xffffffffu, as1, 1); as1 += __shfl_xor_sync(0xffffffffu, as1, 2);
        ad1 += __shfl_xor_sync(0xffffffffu, ad1, 1); ad1 += __shfl_xor_sync(0xffffffffu, ad1, 2);
        if (t4 == 0) {
            int row0 = rowBase + lrow0;
            g_asrc[row0 * 4 + head] = as0;
            g_adst[row0 * 4 + head] = ad0;
            g_asrc[(row0 + 8) * 4 + head] = as1;
            g_adst[(row0 + 8) * 4 + head] = ad1;
        }
    }

    // transpose h through smem (aliased over sX) -> coalesced STG.128
    __syncthreads();                             // all sX reads complete
#pragma unroll
    for (int nt = 0; nt < 8; nt++) {
        int ch = ng * 32 + nt * 4 + t4;          // half2 column index
        sH[lrow0 * HROW + ch]       = __floats2half2_rn(acc[nt][0], acc[nt][1]);
        sH[(lrow0 + 8) * HROW + ch] = __floats2half2_rn(acc[nt][2], acc[nt][3]);
    }
    __syncthreads();
    {
        int orow = t >> 3, oc = t & 7;           // 8 threads per row
        const __half2* src = sH + orow * HROW + oc * 16;
        uint4* dst = g_hv + (size_t)(rowBase + orow) * 32 + oc * 4;
#pragma unroll
        for (int j = 0; j < 4; j++)
            dst[j] = *(const uint4*)(src + j * 4);
    }
}

// ---------------- softmax aggregation (single pass, one warp per (r, dst)) ----
// Best-measured agg structure; int32 indexing (all offsets < 2^20) to kill
// IMAD.WIDE chains; unroll 4 for load MLP. No max-shift: logits bounded far
// below 80, so exp(e) equals the reference's shifted softmax; den eps 1e-16.
__global__ __launch_bounds__(256) void k_agg(const float* __restrict__ bias,
                                             float* __restrict__ out) {
    int gw = (blockIdx.x * blockDim.x + threadIdx.x) >> 5;
    int lane = threadIdx.x & 31;
    if (gw >= RN) return;
    int r = gw / N_NODES, i = gw - r * N_NODES;
    int head = lane >> 3;
    int cnt = g_cursor[i];
    const int* bkt = g_bkt + i * BKT;
    int rbase = r * N_NODES;
    const float* asrcp = g_asrc + rbase * 4 + head;
    const uint4* hvp = g_hv + (size_t)rbase * 32 + lane;

    float adsth = g_adst[(rbase + i) * 4 + head];

    float den = 1e-16f;
    unsigned long long acc[4] = {0ULL, 0ULL, 0ULL, 0ULL};

#pragma unroll 4
    for (int k = 0; k < cnt; k++) {
        int s = bkt[k];
        float e = asrcp[s * 4] + adsth;          // int32 offset
        e = (e > 0.f) ? e : 0.2f * e;
        float w = __expf(fminf(e, 80.f));
        den += w;
        F2U wp; wp.f = make_float2(w, w);
        uint4 u = hvp[s * 32];                   // int32 offset; 16B/lane
        F2U f0, f1, f2, f3;
        f0.f = __half22float2(*reinterpret_cast<__half2*>(&u.x));
        f1.f = __half22float2(*reinterpret_cast<__half2*>(&u.y));
        f2.f = __half22float2(*reinterpret_cast<__half2*>(&u.z));
        f3.f = __half22float2(*reinterpret_cast<__half2*>(&u.w));
        acc[0] = fma2(wp.u, f0.u, acc[0]);
        acc[1] = fma2(wp.u, f1.u, acc[1]);
        acc[2] = fma2(wp.u, f2.u, acc[2]);
        acc[3] = fma2(wp.u, f3.u, acc[3]);
    }

    float inv = 1.0f / den;
    float a[8];
#pragma unroll
    for (int j = 0; j < 4; j++) {
        F2U u; u.u = acc[j];
        a[2 * j] = u.f.x * inv; a[2 * j + 1] = u.f.y * inv;
    }

    // head mean: lanes l, l^8, l^16, l^24 hold same channel, different heads
#pragma unroll
    for (int k = 0; k < 8; k++) {
        a[k] += __shfl_xor_sync(0xffffffffu, a[k], 8);
        a[k] += __shfl_xor_sync(0xffffffffu, a[k], 16);
    }

    if (lane < 8) {
        const float4* bp = (const float4*)bias;
        float4 b0 = bp[lane * 2], b1 = bp[lane * 2 + 1];
        float4 o0 = make_float4(0.25f * a[0] + b0.x, 0.25f * a[1] + b0.y,
                                0.25f * a[2] + b0.z, 0.25f * a[3] + b0.w);
        float4 o1 = make_float4(0.25f * a[4] + b1.x, 0.25f * a[5] + b1.y,
                                0.25f * a[6] + b1.z, 0.25f * a[7] + b1.w);
        float4* op = (float4*)(out + (size_t)(rbase + i) * 64 + lane * 8);
        op[0] = o0;
        op[1] = o1;
    }
}

// ---------------- launch ------------------------------------------------------
extern "C" void kernel_launch(void* const* d_in, const int* in_sizes, int n_in,
                              void* d_out, int out_size) {
    const float* x    = (const float*)d_in[0];
    const void*  ei   = d_in[1];
    const float* W    = (const float*)d_in[2];
    const float* attS = (const float*)d_in[3];
    const float* attD = (const float*)d_in[4];
    const float* bias = (const float*)d_in[5];
    float* out = (float*)d_out;

    k_prep<<<36, 256>>>(W);                            // W split + bucket init
    k_scatter<<<(E_IN + 255) / 256, 256>>>(ei);        // bucketed edge scatter
    k_gemm<<<RN / 32, 256>>>(x, attS, attD);
    k_agg<<<RN / 8, 256>>>(bias, out);
}

// round 16
// speedup vs baseline: 1.0905x; 1.0905x over previous
#include <cuda_runtime.h>
#include <cuda_fp16.h>
#include <cstdint>

#define R_TOT   48
#define N_NODES 1000
#define RN      48000          // R_TOT * N_NODES
#define E_IN    12000
#define F_DIM   64
#define HC      256            // H * C
#define H_HEADS 4
#define BKT     96             // bucket capacity: mean deg 12, 24 sigma margin

// ---------------- scratch (static device globals; no allocation) -------------
// h stored as fp16, row-major [RN][256] halves (viewed as [RN][32] uint4 by k_agg)
__device__ uint4  g_hv[(size_t)RN * 32];
__device__ float  g_asrc[RN * H_HEADS];
__device__ float  g_adst[RN * H_HEADS];
__device__ float4 g_Wf[8 * 32 * 32];    // pre-split W fragments: [kstep][ntile][lane]
__device__ int    g_cursor[N_NODES];    // bucket fill count (init 1 by k_prep)
__device__ int    g_bkt[N_NODES * BKT]; // incoming-edge sources per node
__device__ int    g_is32;

// ---------------- packed / tf32 helpers ---------------------------------------
union F2U { unsigned long long u; float2 f; };
__device__ __forceinline__ unsigned long long fma2(unsigned long long a,
                                                   unsigned long long b,
                                                   unsigned long long c) {
    unsigned long long d;
    asm("fma.rn.f32x2 %0, %1, %2, %3;" : "=l"(d) : "l"(a), "l"(b), "l"(c));
    return d;
}

__device__ __forceinline__ unsigned tf32_rna(float v) {
    unsigned r;
    asm("cvt.rna.tf32.f32 %0, %1;" : "=r"(r) : "f"(v));
    return r;
}

#define MMA_TF32(d, a, b0, b1)                                                  \
    asm volatile("mma.sync.aligned.m16n8k8.row.col.f32.tf32.tf32.f32 "          \
                 "{%0,%1,%2,%3}, {%4,%5,%6,%7}, {%8,%9}, {%0,%1,%2,%3};"        \
                 : "+f"((d)[0]), "+f"((d)[1]), "+f"((d)[2]), "+f"((d)[3])       \
                 : "r"((a)[0]), "r"((a)[1]), "r"((a)[2]), "r"((a)[3]),          \
                   "r"(b0), "r"(b1))

// ---------------- prep: W split + bucket init ----------------------------------
// Blocks [0,32): pre-split W into mma B-fragment order.
// Blocks [32,36): per-node cursor=1 and self-loop in slot 0 (deterministic).
// Original self-loops are dropped (reference masks them to -inf => exp == 0).
__global__ __launch_bounds__(256) void k_prep(const float* __restrict__ W) {
    int t = threadIdx.x;
    if (blockIdx.x < 32) {
        int i = blockIdx.x * 256 + t;            // 0..8191
        int lane = i & 31, ntg = (i >> 5) & 31, ks = i >> 10;
        int t4 = lane & 3, g = lane >> 2;
        int col = ntg * 8 + g;
        float b0 = W[(ks * 8 + t4) * HC + col];
        float b1 = W[(ks * 8 + t4 + 4) * HC + col];
        unsigned b0h = tf32_rna(b0), b1h = tf32_rna(b1);
        unsigned b0l = tf32_rna(b0 - __uint_as_float(b0h));
        unsigned b1l = tf32_rna(b1 - __uint_as_float(b1h));
        g_Wf[i] = make_float4(__uint_as_float(b0h), __uint_as_float(b1h),
                              __uint_as_float(b0l), __uint_as_float(b1l));
        return;
    }
    int i = (blockIdx.x - 32) * 256 + t;
    if (i < N_NODES) {
        g_cursor[i] = 1;
        g_bkt[i * BKT] = i;              // added self-loop, slot 0
    }
}

// Width detect by sampling: if edge_index is int64 (values < 1000), EVERY odd
// 32-bit word is zero. 32 sampled odd words all zero on int32 random data has
// probability ~1e-96. Sampled positions stay within the first 24000 words.
__device__ __forceinline__ int detect_is32_warp(const int* e32, int lane) {
    int f = (e32[2 * (lane * 375) + 1] != 0);
    unsigned b = __ballot_sync(0xffffffffu, f);
    return b != 0;
}

// Single-pass bucketed scatter: p = atomicAdd(cursor[d]); bkt[d*BKT+p] = s.
__global__ __launch_bounds__(256) void k_scatter(const void* __restrict__ ei) {
    __shared__ int s_is32;
    const int* e32 = (const int*)ei;
    const long long* e64 = (const long long*)ei;
    int t = threadIdx.x;
    if (t < 32) {
        int is32 = detect_is32_warp(e32, t);
        if (t == 0) s_is32 = is32;
    }
    __syncthreads();
    int is32 = s_is32;
    int e = blockIdx.x * 256 + t;
    if (e < E_IN) {
        int s = is32 ? e32[e] : (int)e64[e];
        int d = is32 ? e32[E_IN + e] : (int)e64[E_IN + e];
        if (s != d) {
            int p = atomicAdd(&g_cursor[d], 1);
            if (p < BKT) g_bkt[d * BKT + p] = s;
        }
    }
}

// ---------------- projection GEMM (tensor cores, 2-term TF32) + logits --------
// Warp tile 16 rows x 64 cols (one m16 tile), 4 blocks/SM, grid 1500.
// A-path: x tile staged in smem (coalesced in, conflict-free LDS out).
// D = Xhi*Whi + Xhi*Wlo (X-lo term dropped: its contribution is <= 2^-11
// relative — the same scale as the fp16 rounding of h we already accept).
// Epilogue: results transposed through smem -> coalesced STG.128.
// One head per warp -> logits close with a 4-lane quad reduction.
#define HROW 132                         // half2 stride per row (528B, conflict-free)
__global__ __launch_bounds__(256, 4) void k_gemm(const float* __restrict__ x,
                                                 const float* __restrict__ attS,
                                                 const float* __restrict__ attD) {
    __shared__ __align__(16) char s_buf[32 * HROW * 4];   // 16.9 KB (sX then sH)
    __shared__ float sAS[HC], sAD[HC];
    float* sX = (float*)s_buf;            // 32 rows x stride 68 floats (8.7 KB)
    __half2* sH = (__half2*)s_buf;        // 32 rows x stride 132 half2
    int t = threadIdx.x, warp = t >> 5, lane = t & 31;
    int g = lane >> 2, t4 = lane & 3;
    int mg = warp >> 2, ng = warp & 3;
    int rowBase = blockIdx.x * 32;

    // stage x tile: 32 rows x 16 float4, 2 per thread, coalesced
    for (int i = t; i < 32 * 16; i += 256) {
        int row = i >> 4, j4 = i & 15;
        float4 v = ((const float4*)(x + (size_t)(rowBase + row) * F_DIM))[j4];
        *(float4*)&sX[row * 68 + j4 * 4] = v;
    }
    if (t < HC) { sAS[t] = attS[t]; sAD[t] = attD[t]; }
    __syncthreads();

    float acc[8][4];
#pragma unroll
    for (int nt = 0; nt < 8; nt++)
#pragma unroll
        for (int j = 0; j < 4; j++) acc[nt][j] = 0.f;

    const float* xr0 = sX + (mg * 16 + g) * 68 + t4;

#pragma unroll
    for (int ks = 0; ks < 8; ks++) {
        unsigned ah[4];
        {
            const float* xr = xr0 + ks * 8;
            ah[0] = tf32_rna(xr[0]);         // (row g,    col t4)
            ah[1] = tf32_rna(xr[8 * 68]);    // (row g+8,  col t4)
            ah[2] = tf32_rna(xr[4]);         // (row g,    col t4+4)
            ah[3] = tf32_rna(xr[8 * 68 + 4]);
        }
#pragma unroll
        for (int nt = 0; nt < 8; nt++) {
            float4 b = g_Wf[((size_t)ks * 32 + ng * 8 + nt) * 32 + lane];  // LDG.128
            unsigned b0h = __float_as_uint(b.x), b1h = __float_as_uint(b.y);
            unsigned b0l = __float_as_uint(b.z), b1l = __float_as_uint(b.w);
            MMA_TF32(acc[nt], ah, b0h, b1h);
            MMA_TF32(acc[nt], ah, b0l, b1l);
        }
    }

    // logits for this warp's head (= ng) from register fragments
    int head = ng, n0 = ng * 64;
    int lrow0 = mg * 16 + g;                     // local rows lrow0, lrow0+8
    {
        float as0 = 0.f, ad0 = 0.f, as1 = 0.f, ad1 = 0.f;
#pragma unroll
        for (int nt = 0; nt < 8; nt++) {
            int c = n0 + nt * 8 + 2 * t4;
            float* a = acc[nt];
            as0 += a[0] * sAS[c] + a[1] * sAS[c + 1];
            ad0 += a[0] * sAD[c] + a[1] * sAD[c + 1];
            as1 += a[2] * sAS[c] + a[3] * sAS[c + 1];
            ad1 += a[2] * sAD[c] + a[3] * sAD[c + 1];
        }
        as0 += __shfl_xor_sync(0xffffffffu, as0, 1); as0 += __shfl_xor_sync(0xffffffffu, as0, 2);
        ad0 += __shfl_xor_sync(0xffffffffu, ad0, 1); ad0 += __shfl_xor_sync(0xffffffffu, ad0, 2);
        as1 += __shfl_xor_sync(0xffffffffu, as1, 1); as1 += __shfl_xor_sync(0xffffffffu, as1, 2);
        ad1 += __shfl_xor_sync(0xffffffffu, ad1, 1); ad1 += __shfl_xor_sync(0xffffffffu, ad1, 2);
        if (t4 == 0) {
            int row0 = rowBase + lrow0;
            g_asrc[row0 * 4 + head] = as0;
            g_adst[row0 * 4 + head] = ad0;
            g_asrc[(row0 + 8) * 4 + head] = as1;
            g_adst[(row0 + 8) * 4 + head] = ad1;
        }
    }

    // transpose h through smem (aliased over sX) -> coalesced STG.128
    __syncthreads();                             // all sX reads complete
#pragma unroll
    for (int nt = 0; nt < 8; nt++) {
        int ch = ng * 32 + nt * 4 + t4;          // half2 column index
        sH[lrow0 * HROW + ch]       = __floats2half2_rn(acc[nt][0], acc[nt][1]);
        sH[(lrow0 + 8) * HROW + ch] = __floats2half2_rn(acc[nt][2], acc[nt][3]);
    }
    __syncthreads();
    {
        int orow = t >> 3, oc = t & 7;           // 8 threads per row
        const __half2* src = sH + orow * HROW + oc * 16;
        uint4* dst = g_hv + (size_t)(rowBase + orow) * 32 + oc * 4;
#pragma unroll
        for (int j = 0; j < 4; j++)
            dst[j] = *(const uint4*)(src + j * 4);
    }
}

// ---------------- softmax aggregation (single pass, one warp per (r, dst)) ----
// Best-measured agg structure (R13 unroll, int32 indexing, packed fma2).
// No max-shift: logits bounded far below 80, so exp(e) equals the reference's
// shifted softmax; den eps 1e-16 matches ref.
__global__ __launch_bounds__(256) void k_agg(const float* __restrict__ bias,
                                             float* __restrict__ out) {
    int gw = (blockIdx.x * blockDim.x + threadIdx.x) >> 5;
    int lane = threadIdx.x & 31;
    if (gw >= RN) return;
    int r = gw / N_NODES, i = gw - r * N_NODES;
    int head = lane >> 3;
    int cnt = g_cursor[i];
    const int* bkt = g_bkt + i * BKT;
    int rbase = r * N_NODES;
    const float* asrcp = g_asrc + rbase * 4 + head;
    const uint4* hvp = g_hv + (size_t)rbase * 32 + lane;

    float adsth = g_adst[(rbase + i) * 4 + head];

    float den = 1e-16f;
    unsigned long long acc[4] = {0ULL, 0ULL, 0ULL, 0ULL};

#pragma unroll 2
    for (int k = 0; k < cnt; k++) {
        int s = bkt[k];
        float e = asrcp[s * 4] + adsth;          // int32 offset
        e = (e > 0.f) ? e : 0.2f * e;
        float w = __expf(fminf(e, 80.f));
        den += w;
        F2U wp; wp.f = make_float2(w, w);
        uint4 u = hvp[s * 32];                   // int32 offset; 16B/lane
        F2U f0, f1, f2, f3;
        f0.f = __half22float2(*reinterpret_cast<__half2*>(&u.x));
        f1.f = __half22float2(*reinterpret_cast<__half2*>(&u.y));
        f2.f = __half22float2(*reinterpret_cast<__half2*>(&u.z));
        f3.f = __half22float2(*reinterpret_cast<__half2*>(&u.w));
        acc[0] = fma2(wp.u, f0.u, acc[0]);
        acc[1] = fma2(wp.u, f1.u, acc[1]);
        acc[2] = fma2(wp.u, f2.u, acc[2]);
        acc[3] = fma2(wp.u, f3.u, acc[3]);
    }

    float inv = 1.0f / den;
    float a[8];
#pragma unroll
    for (int j = 0; j < 4; j++) {
        F2U u; u.u = acc[j];
        a[2 * j] = u.f.x * inv; a[2 * j + 1] = u.f.y * inv;
    }

    // head mean: lanes l, l^8, l^16, l^24 hold same channel, different heads
#pragma unroll
    for (int k = 0; k < 8; k++) {
        a[k] += __shfl_xor_sync(0xffffffffu, a[k], 8);
        a[k] += __shfl_xor_sync(0xffffffffu, a[k], 16);
    }

    if (lane < 8) {
        const float4* bp = (const float4*)bias;
        float4 b0 = bp[lane * 2], b1 = bp[lane * 2 + 1];
        float4 o0 = make_float4(0.25f * a[0] + b0.x, 0.25f * a[1] + b0.y,
                                0.25f * a[2] + b0.z, 0.25f * a[3] + b0.w);
        float4 o1 = make_float4(0.25f * a[4] + b1.x, 0.25f * a[5] + b1.y,
                                0.25f * a[6] + b1.z, 0.25f * a[7] + b1.w);
        float4* op = (float4*)(out + (size_t)(rbase + i) * 64 + lane * 8);
        op[0] = o0;
        op[1] = o1;
    }
}

// ---------------- launch ------------------------------------------------------
extern "C" void kernel_launch(void* const* d_in, const int* in_sizes, int n_in,
                              void* d_out, int out_size) {
    const float* x    = (const float*)d_in[0];
    const void*  ei   = d_in[1];
    const float* W    = (const float*)d_in[2];
    const float* attS = (const float*)d_in[3];
    const float* attD = (const float*)d_in[4];
    const float* bias = (const float*)d_in[5];
    float* out = (float*)d_out;

    k_prep<<<36, 256>>>(W);                            // W split + bucket init
    k_scatter<<<(E_IN + 255) / 256, 256>>>(ei);        // bucketed edge scatter
    k_gemm<<<RN / 32, 256>>>(x, attS, attD);
    k_agg<<<RN / 8, 256>>>(bias, out);
}

// round 17
// speedup vs baseline: 1.2557x; 1.1515x over previous
#include <cuda_runtime.h>
#include <cuda_fp16.h>
#include <cstdint>

#define R_TOT   48
#define N_NODES 1000
#define RN      48000          // R_TOT * N_NODES
#define E_IN    12000
#define F_DIM   64
#define HC      256            // H * C
#define H_HEADS 4
#define BKT     96             // bucket capacity: mean deg 12, 24 sigma margin

// ---------------- scratch (static device globals; no allocation) -------------
// h stored as fp16, row-major [RN][256] halves (viewed as [RN][32] uint4 by k_agg)
__device__ uint4  g_hv[(size_t)RN * 32];
__device__ float  g_asrc[RN * H_HEADS];
__device__ float  g_adst[RN * H_HEADS];
__device__ uint2  g_Wh[4 * 32 * 32];    // fp16 B fragments: [ks16][ntile][lane] (32 KB)
__device__ int    g_cursor[N_NODES];    // bucket fill count (init 1 by k_prep)
__device__ int    g_bkt[N_NODES * BKT]; // incoming-edge sources per node
__device__ int    g_is32;

// ---------------- packed helpers ----------------------------------------------
union F2U { unsigned long long u; float2 f; };
__device__ __forceinline__ unsigned long long fma2(unsigned long long a,
                                                   unsigned long long b,
                                                   unsigned long long c) {
    unsigned long long d;
    asm("fma.rn.f32x2 %0, %1, %2, %3;" : "=l"(d) : "l"(a), "l"(b), "l"(c));
    return d;
}

// fp16 tensor-core MMA, fp32 accumulate. C fragment layout identical to the
// m16n8k8 tf32 form (c0,c1 = row g cols 2t4..; c2,c3 = row g+8).
#define MMA_F16(d, a0, a1, a2, a3, b0, b1)                                      \
    asm volatile("mma.sync.aligned.m16n8k16.row.col.f32.f16.f16.f32 "           \
                 "{%0,%1,%2,%3}, {%4,%5,%6,%7}, {%8,%9}, {%0,%1,%2,%3};"        \
                 : "+f"((d)[0]), "+f"((d)[1]), "+f"((d)[2]), "+f"((d)[3])       \
                 : "r"(a0), "r"(a1), "r"(a2), "r"(a3), "r"(b0), "r"(b1))

// ---------------- prep: W split (fp16 B fragments) + bucket init ---------------
// Blocks [0,16): W -> fp16 B-fragment table.
//   m16n8k16 .col B fragment: lane l (t4=l&3, g=l>>2):
//     b0 = {W[k0+2t4][n], W[k0+2t4+1][n]},  b1 = {W[k0+2t4+8][n], W[k0+2t4+9][n]}
// Blocks [16,20): per-node cursor=1 and self-loop in slot 0 (deterministic).
// Original self-loops are dropped (reference masks them to -inf => exp == 0).
__global__ __launch_bounds__(256) void k_prep(const float* __restrict__ W) {
    int t = threadIdx.x;
    if (blockIdx.x < 16) {
        int i = blockIdx.x * 256 + t;            // 0..4095
        int lane = i & 31, ntg = (i >> 5) & 31, ks = i >> 10;   // ks16 in 0..3
        int t4 = lane & 3, g = lane >> 2;
        int col = ntg * 8 + g;
        int k0 = ks * 16 + 2 * t4;
        __half2 b0 = __floats2half2_rn(W[k0 * HC + col],       W[(k0 + 1) * HC + col]);
        __half2 b1 = __floats2half2_rn(W[(k0 + 8) * HC + col], W[(k0 + 9) * HC + col]);
        uint2 u;
        u.x = *reinterpret_cast<unsigned*>(&b0);
        u.y = *reinterpret_cast<unsigned*>(&b1);
        g_Wh[i] = u;
        return;
    }
    int i = (blockIdx.x - 16) * 256 + t;
    if (i < N_NODES) {
        g_cursor[i] = 1;
        g_bkt[i * BKT] = i;              // added self-loop, slot 0
    }
}

// Width detect by sampling: if edge_index is int64 (values < 1000), EVERY odd
// 32-bit word is zero. 32 sampled odd words all zero on int32 random data has
// probability ~1e-96. Sampled positions stay within the first 24000 words.
__device__ __forceinline__ int detect_is32_warp(const int* e32, int lane) {
    int f = (e32[2 * (lane * 375) + 1] != 0);
    unsigned b = __ballot_sync(0xffffffffu, f);
    return b != 0;
}

// Single-pass bucketed scatter: p = atomicAdd(cursor[d]); bkt[d*BKT+p] = s.
__global__ __launch_bounds__(256) void k_scatter(const void* __restrict__ ei) {
    __shared__ int s_is32;
    const int* e32 = (const int*)ei;
    const long long* e64 = (const long long*)ei;
    int t = threadIdx.x;
    if (t < 32) {
        int is32 = detect_is32_warp(e32, t);
        if (t == 0) s_is32 = is32;
    }
    __syncthreads();
    int is32 = s_is32;
    int e = blockIdx.x * 256 + t;
    if (e < E_IN) {
        int s = is32 ? e32[e] : (int)e64[e];
        int d = is32 ? e32[E_IN + e] : (int)e64[E_IN + e];
        if (s != d) {
            int p = atomicAdd(&g_cursor[d], 1);
            if (p < BKT) g_bkt[d * BKT + p] = s;
        }
    }
}

// ---------------- projection GEMM (fp16 HMMA, fp32 accum) + logits -------------
// Warp tile 16 rows x 64 cols, 4 blocks/SM, grid 1500.
// x staged in smem pre-converted to half2 (stride 36 half2, conflict-free LDS).
// fp16 inputs have the same 10-bit mantissa as tf32: X error unchanged vs the
// 2-term tf32 version; W adds one 2^-11-scale term (measured budget 1e-3).
// Inner loop per warp: 4 ks16 x (4 LDS.32 + 8 LDG.64 + 8 MMA) — ~3x fewer
// issue slots and 4x less fragment traffic than the tf32 version.
// Epilogue: logits (4-lane quad reduce) + smem transpose -> coalesced STG.128.
#define HROW 132                         // half2 stride per row (528B, conflict-free)
#define XROW 36                          // half2 stride for staged x rows
__global__ __launch_bounds__(256, 4) void k_gemm(const float* __restrict__ x,
                                                 const float* __restrict__ attS,
                                                 const float* __restrict__ attD) {
    __shared__ __align__(16) char s_buf[32 * HROW * 4];   // 16.9 KB (sXh then sH)
    __shared__ float sAS[HC], sAD[HC];
    unsigned* sXh = (unsigned*)s_buf;     // 32 rows x stride 36 half2 (4.6 KB)
    __half2* sH = (__half2*)s_buf;        // 32 rows x stride 132 half2 (epilogue)
    int t = threadIdx.x, warp = t >> 5, lane = t & 31;
    int g = lane >> 2, t4 = lane & 3;
    int mg = warp >> 2, ng = warp & 3;
    int rowBase = blockIdx.x * 32;

    // stage x tile as half2: 32 rows x 16 float4 in, 2 half2 out per float4
    for (int i = t; i < 32 * 16; i += 256) {
        int row = i >> 4, j4 = i & 15;
        float4 v = ((const float4*)(x + (size_t)(rowBase + row) * F_DIM))[j4];
        __half2 p0 = __floats2half2_rn(v.x, v.y);
        __half2 p1 = __floats2half2_rn(v.z, v.w);
        uint2 u;
        u.x = *reinterpret_cast<unsigned*>(&p0);
        u.y = *reinterpret_cast<unsigned*>(&p1);
        *(uint2*)&sXh[row * XROW + j4 * 2] = u;
    }
    if (t < HC) { sAS[t] = attS[t]; sAD[t] = attD[t]; }
    __syncthreads();

    float acc[8][4];
#pragma unroll
    for (int nt = 0; nt < 8; nt++)
#pragma unroll
        for (int j = 0; j < 4; j++) acc[nt][j] = 0.f;

    const unsigned* xr0 = sXh + (mg * 16 + g) * XROW + t4;

#pragma unroll
    for (int ks = 0; ks < 4; ks++) {
        // A fragment (m16n8k16 .row): a0=[g][2t4..], a1=[g+8][2t4..],
        //                             a2=[g][2t4+8..], a3=[g+8][2t4+8..]
        unsigned a0 = xr0[ks * 8];
        unsigned a1 = xr0[8 * XROW + ks * 8];
        unsigned a2 = xr0[ks * 8 + 4];
        unsigned a3 = xr0[8 * XROW + ks * 8 + 4];
#pragma unroll
        for (int nt = 0; nt < 8; nt++) {
            uint2 b = g_Wh[(ks * 32 + ng * 8 + nt) * 32 + lane];   // LDG.64
            MMA_F16(acc[nt], a0, a1, a2, a3, b.x, b.y);
        }
    }

    // logits for this warp's head (= ng) from register fragments
    int head = ng, n0 = ng * 64;
    int lrow0 = mg * 16 + g;                     // local rows lrow0, lrow0+8
    {
        float as0 = 0.f, ad0 = 0.f, as1 = 0.f, ad1 = 0.f;
#pragma unroll
        for (int nt = 0; nt < 8; nt++) {
            int c = n0 + nt * 8 + 2 * t4;
            float* a = acc[nt];
            as0 += a[0] * sAS[c] + a[1] * sAS[c + 1];
            ad0 += a[0] * sAD[c] + a[1] * sAD[c + 1];
            as1 += a[2] * sAS[c] + a[3] * sAS[c + 1];
            ad1 += a[2] * sAD[c] + a[3] * sAD[c + 1];
        }
        as0 += __shfl_xor_sync(0xffffffffu, as0, 1); as0 += __shfl_xor_sync(0xffffffffu, as0, 2);
        ad0 += __shfl_xor_sync(0xffffffffu, ad0, 1); ad0 += __shfl_xor_sync(0xffffffffu, ad0, 2);
        as1 += __shfl_xor_sync(0xffffffffu, as1, 1); as1 += __shfl_xor_sync(0xffffffffu, as1, 2);
        ad1 += __shfl_xor_sync(0xffffffffu, ad1, 1); ad1 += __shfl_xor_sync(0xffffffffu, ad1, 2);
        if (t4 == 0) {
            int row0 = rowBase + lrow0;
            g_asrc[row0 * 4 + head] = as0;
            g_adst[row0 * 4 + head] = ad0;
            g_asrc[(row0 + 8) * 4 + head] = as1;
            g_adst[(row0 + 8) * 4 + head] = ad1;
        }
    }

    // transpose h through smem (aliased over sXh) -> coalesced STG.128
    __syncthreads();                             // all sXh reads complete
#pragma unroll
    for (int nt = 0; nt < 8; nt++) {
        int ch = ng * 32 + nt * 4 + t4;          // half2 column index
        sH[lrow0 * HROW + ch]       = __floats2half2_rn(acc[nt][0], acc[nt][1]);
        sH[(lrow0 + 8) * HROW + ch] = __floats2half2_rn(acc[nt][2], acc[nt][3]);
    }
    __syncthreads();
    {
        int orow = t >> 3, oc = t & 7;           // 8 threads per row
        const __half2* src = sH + orow * HROW + oc * 16;
        uint4* dst = g_hv + (size_t)(rowBase + orow) * 32 + oc * 4;
#pragma unroll
        for (int j = 0; j < 4; j++)
            dst[j] = *(const uint4*)(src + j * 4);
    }
}

// ---------------- softmax aggregation (single pass, one warp per (r, dst)) ----
// Best-measured agg structure (frozen): int32 indexing, packed fma2, unroll 2.
// No max-shift: logits bounded far below 80, so exp(e) equals the reference's
// shifted softmax; den eps 1e-16 matches ref.
__global__ __launch_bounds__(256) void k_agg(const float* __restrict__ bias,
                                             float* __restrict__ out) {
    int gw = (blockIdx.x * blockDim.x + threadIdx.x) >> 5;
    int lane = threadIdx.x & 31;
    if (gw >= RN) return;
    int r = gw / N_NODES, i = gw - r * N_NODES;
    int head = lane >> 3;
    int cnt = g_cursor[i];
    const int* bkt = g_bkt + i * BKT;
    int rbase = r * N_NODES;
    const float* asrcp = g_asrc + rbase * 4 + head;
    const uint4* hvp = g_hv + (size_t)rbase * 32 + lane;

    float adsth = g_adst[(rbase + i) * 4 + head];

    float den = 1e-16f;
    unsigned long long acc[4] = {0ULL, 0ULL, 0ULL, 0ULL};

#pragma unroll 2
    for (int k = 0; k < cnt; k++) {
        int s = bkt[k];
        float e = asrcp[s * 4] + adsth;          // int32 offset
        e = (e > 0.f) ? e : 0.2f * e;
        float w = __expf(fminf(e, 80.f));
        den += w;
        F2U wp; wp.f = make_float2(w, w);
        uint4 u = hvp[s * 32];                   // int32 offset; 16B/lane
        F2U f0, f1, f2, f3;
        f0.f = __half22float2(*reinterpret_cast<__half2*>(&u.x));
        f1.f = __half22float2(*reinterpret_cast<__half2*>(&u.y));
        f2.f = __half22float2(*reinterpret_cast<__half2*>(&u.z));
        f3.f = __half22float2(*reinterpret_cast<__half2*>(&u.w));
        acc[0] = fma2(wp.u, f0.u, acc[0]);
        acc[1] = fma2(wp.u, f1.u, acc[1]);
        acc[2] = fma2(wp.u, f2.u, acc[2]);
        acc[3] = fma2(wp.u, f3.u, acc[3]);
    }

    float inv = 1.0f / den;
    float a[8];
#pragma unroll
    for (int j = 0; j < 4; j++) {
        F2U u; u.u = acc[j];
        a[2 * j] = u.f.x * inv; a[2 * j + 1] = u.f.y * inv;
    }

    // head mean: lanes l, l^8, l^16, l^24 hold same channel, different heads
#pragma unroll
    for (int k = 0; k < 8; k++) {
        a[k] += __shfl_xor_sync(0xffffffffu, a[k], 8);
        a[k] += __shfl_xor_sync(0xffffffffu, a[k], 16);
    }

    if (lane < 8) {
        const float4* bp = (const float4*)bias;
        float4 b0 = bp[lane * 2], b1 = bp[lane * 2 + 1];
        float4 o0 = make_float4(0.25f * a[0] + b0.x, 0.25f * a[1] + b0.y,
                                0.25f * a[2] + b0.z, 0.25f * a[3] + b0.w);
        float4 o1 = make_float4(0.25f * a[4] + b1.x, 0.25f * a[5] + b1.y,
                                0.25f * a[6] + b1.z, 0.25f * a[7] + b1.w);
        float4* op = (float4*)(out + (size_t)(rbase + i) * 64 + lane * 8);
        op[0] = o0;
        op[1] = o1;
    }
}

// ---------------- launch ------------------------------------------------------
extern "C" void kernel_launch(void* const* d_in, const int* in_sizes, int n_in,
                              void* d_out, int out_size) {
    const float* x    = (const float*)d_in[0];
    const void*  ei   = d_in[1];
    const float* W    = (const float*)d_in[2];
    const float* attS = (const float*)d_in[3];
    const float* attD = (const float*)d_in[4];
    const float* bias = (const float*)d_in[5];
    float* out = (float*)d_out;

    k_prep<<<20, 256>>>(W);                            // fp16 W split + bucket init
    k_scatter<<<(E_IN + 255) / 256, 256>>>(ei);        // bucketed edge scatter
    k_gemm<<<RN / 32, 256>>>(x, attS, attD);
    k_agg<<<RN / 8, 256>>>(bias, out);
}